// round 8
// baseline (speedup 1.0000x reference)
#include <cuda_runtime.h>
#include <cuda_bf16.h>
#include <math.h>
#include <stdint.h>

#define DIM  256
#define NH   4
#define HC   64
#define NTOK 49
#define NB   4096

// Standardized weights in ks-paired mma-FRAGMENT order:
// uint4 index = (nblk*8 + kp)*32 + lane ; uint4 = {ks_even half0, ks_even half1,
//                                                  ks_odd half0,  ks_odd half1}
// For col c, k: nblk=c>>3, lane=(c&7)*4+((k>>1)&3), kp=k>>5, kodd=(k>>4)&1,
//               half=(k>>3)&1, par=k&1.
__device__ __align__(16) __nv_bfloat16 g_Wbf[5][DIM * DIM];
__device__ float g_b[5][DIM];

#define W_MAT_U4 8192   // uint4 per 256x256 bf16 matrix

// ---------------------------------------------------------------------------
// Prologue: weight standardization -> ks-paired fragment-ordered bf16
// ---------------------------------------------------------------------------
__global__ __launch_bounds__(256) void std_kernel(
    const float* __restrict__ qw, const float* __restrict__ qb,
    const float* __restrict__ kw, const float* __restrict__ kb,
    const float* __restrict__ vw, const float* __restrict__ vb,
    const float* __restrict__ fiw, const float* __restrict__ fib,
    const float* __restrict__ fow, const float* __restrict__ fob)
{
    const float* wptr[5] = {qw, kw, vw, fiw, fow};
    const float* bptr[5] = {qb, kb, vb, fib, fob};
    __shared__ float s_sum[8], s_sq[8];
    int bx = blockIdx.x, t = threadIdx.x;

    float val;
    if (bx < 5 * DIM) val = wptr[bx >> 8][(bx & 255) * DIM + t];
    else              val = bptr[bx - 5 * DIM][t];

    float s = val, q = val * val;
    #pragma unroll
    for (int o = 16; o > 0; o >>= 1) {
        s += __shfl_xor_sync(0xFFFFFFFFu, s, o);
        q += __shfl_xor_sync(0xFFFFFFFFu, q, o);
    }
    if ((t & 31) == 0) { s_sum[t >> 5] = s; s_sq[t >> 5] = q; }
    __syncthreads();
    int h = t >> 6;
    float sum = s_sum[2*h] + s_sum[2*h+1];
    float sq  = s_sq [2*h] + s_sq [2*h+1];
    float mean = sum * (1.0f/64.0f);
    float var  = fmaxf(sq * (1.0f/64.0f) - mean*mean, 0.0f);
    float r    = (val - mean) / (sqrtf(var) * 16.0f);

    if (bx < 5 * DIM) {
        int m = bx >> 8, k = bx & 255, c = t;
        int kp   = k >> 5;
        int kodd = (k >> 4) & 1;
        int half = (k >> 3) & 1;
        int pos2 = (k >> 1) & 3;
        int par  = k & 1;
        int lane = (c & 7) * 4 + pos2;
        int nblk = c >> 3;
        size_t idx = ((size_t)(((nblk * 8 + kp) * 32 + lane)) << 3)
                   + (size_t)(kodd * 4 + half * 2 + par);
        ((__nv_bfloat16*)g_Wbf)[(size_t)m * DIM * DIM + idx] = __float2bfloat16(r);
    } else {
        g_b[bx - 5 * DIM][t] = r;
    }
}

// ---------------------------------------------------------------------------
// PTX helpers (baseline PTX only: ldmatrix + mma.sync, sm_80+)
// ---------------------------------------------------------------------------
__device__ __forceinline__ uint32_t s2u(const void* p) {
    uint32_t a;
    asm("{ .reg .u64 t; cvta.to.shared.u64 t, %1; cvt.u32.u64 %0, t; }" : "=r"(a) : "l"(p));
    return a;
}
__device__ __forceinline__ void ldsm4(uint32_t* r, uint32_t a) {
    asm volatile("ldmatrix.sync.aligned.m8n8.x4.shared.b16 {%0,%1,%2,%3}, [%4];"
                 : "=r"(r[0]), "=r"(r[1]), "=r"(r[2]), "=r"(r[3]) : "r"(a));
}
__device__ __forceinline__ void ldsm2(uint32_t* r, uint32_t a) {
    asm volatile("ldmatrix.sync.aligned.m8n8.x2.shared.b16 {%0,%1}, [%2];"
                 : "=r"(r[0]), "=r"(r[1]) : "r"(a));
}
__device__ __forceinline__ void mma16816(float* d, const uint32_t* a, const uint32_t* b) {
    asm volatile("mma.sync.aligned.m16n8k16.row.col.f32.bf16.bf16.f32 "
                 "{%0,%1,%2,%3}, {%4,%5,%6,%7}, {%8,%9}, {%0,%1,%2,%3};"
                 : "+f"(d[0]), "+f"(d[1]), "+f"(d[2]), "+f"(d[3])
                 : "r"(a[0]), "r"(a[1]), "r"(a[2]), "r"(a[3]), "r"(b[0]), "r"(b[1]));
}
__device__ __forceinline__ uint32_t bfx2(float lo, float hi) {   // low half = lo
    uint32_t r;
    asm("cvt.rn.bf16x2.f32 %0, %1, %2;" : "=r"(r) : "f"(hi), "f"(lo));
    return r;
}

// ---------------------------------------------------------------------------
// smem layout (bytes). Activation tiles: 64 rows x 264 bf16, stride 528 B.
// P tiles: per head 64 x 72 bf16 (stride 144 B). VT: 256 x 72 bf16.
// ---------------------------------------------------------------------------
#define RST 260
#define SM_R    0        // 49*260*4 = 50960
#define SM_P    51072    // 36864 : x tile (64x264), later P tiles 4 x (64x72)
#define SM_Q    87936    // 33792 : Q tile, later x2 / t3 tile
#define SM_K    121728   // 33792 : K tile
#define SM_VT   155520   // 36864 : V^T 256 x 72
#define SM_BIAS 192384   // 5120  : biases fp32 [5][256]
#define SMEM_TOTAL 197504

// One 64x256x256 GEMM: warp computes m32 (mh = w>>2) x n64 (nq = w&3).
// A from smem (stride 528, rows mh*32..mh*32+31); B via LDG.128 from
// ks-paired fragment-ordered W. Explicit 1-stage (kp) prefetch pipeline.
__device__ __forceinline__ void mma_gemm(uint32_t aBase, const uint4* __restrict__ Wf,
                                         float acc[2][8][4], uint32_t aoffG)
{
    #pragma unroll
    for (int mf = 0; mf < 2; mf++)
        #pragma unroll
        for (int nf = 0; nf < 8; nf++)
            #pragma unroll
            for (int q = 0; q < 4; q++) acc[mf][nf][q] = 0.0f;

    uint4 breg[2][8];
    uint32_t areg[2][2][2][4];   // [buf][ks-in-pair][mf][frag]

    #pragma unroll
    for (int nf = 0; nf < 8; nf++) breg[0][nf] = __ldg(Wf + nf * 8 * 32);
    #pragma unroll
    for (int mf = 0; mf < 2; mf++) {
        ldsm4(areg[0][0][mf], aBase + aoffG + (uint32_t)(mf * 16 * 528));
        ldsm4(areg[0][1][mf], aBase + aoffG + (uint32_t)(mf * 16 * 528 + 32));
    }

    #pragma unroll
    for (int kp = 0; kp < 8; kp++) {
        const int cur = kp & 1, nxt = cur ^ 1;
        if (kp < 7) {
            #pragma unroll
            for (int nf = 0; nf < 8; nf++)
                breg[nxt][nf] = __ldg(Wf + (nf * 8 + kp + 1) * 32);
            #pragma unroll
            for (int mf = 0; mf < 2; mf++) {
                ldsm4(areg[nxt][0][mf], aBase + aoffG + (uint32_t)(mf * 16 * 528 + (2*kp+2) * 32));
                ldsm4(areg[nxt][1][mf], aBase + aoffG + (uint32_t)(mf * 16 * 528 + (2*kp+3) * 32));
            }
        }
        #pragma unroll
        for (int nf = 0; nf < 8; nf++) {
            uint32_t b0[2] = { breg[cur][nf].x, breg[cur][nf].y };
            uint32_t b1[2] = { breg[cur][nf].z, breg[cur][nf].w };
            #pragma unroll
            for (int mf = 0; mf < 2; mf++) {
                mma16816(acc[mf][nf], areg[cur][0][mf], b0);
                mma16816(acc[mf][nf], areg[cur][1][mf], b1);
            }
        }
    }
}

__global__ __launch_bounds__(256, 1) void irmb_kernel(
    const float* __restrict__ x, float* __restrict__ out)
{
    extern __shared__ char sm[];
    const uint32_t sb = s2u(sm);
    const int tid = threadIdx.x, w = tid >> 5, lane = tid & 31;

    float* R = (float*)(sm + SM_R);
    float* sBias = (float*)(sm + SM_BIAS);

    // zero x/P buffer + VT, load biases
    {
        uint32_t* z = (uint32_t*)(sm + SM_P);
        for (int i = tid; i < 9216; i += 256) z[i] = 0;
        uint32_t* z2 = (uint32_t*)(sm + SM_VT);
        for (int i = tid; i < 9216; i += 256) z2[i] = 0;
        const float* gb = (const float*)g_b;
        for (int i = tid; i < 1280; i += 256) sBias[i] = gb[i];
    }
    const float* xb = x + (size_t)blockIdx.x * (NTOK * DIM);
    float* ob = out + (size_t)blockIdx.x * (NTOK * DIM);
    __syncthreads();

    for (int i = tid; i < NTOK * DIM; i += 256) {
        int r = i >> 8, c = i & 255;
        float v = xb[i];
        R[r * RST + c] = v;
        *(__nv_bfloat16*)(sm + SM_P + r * 528 + c * 2) = __float2bfloat16(v);
    }
    __syncthreads();

    // lane-mapping constants
    const int gq = lane >> 3, iq = lane & 7;
    const uint32_t aoff = (uint32_t)((iq + (gq & 1) * 8) * 528 + ((gq >> 1) * 8) * 2);
    const int r0 = lane >> 2, c0 = 2 * (lane & 3);
    // GEMM warp tiling: mh = m-half, nq = n-quarter
    const int mh = w >> 2, nq = w & 3;
    const uint32_t aoffG = aoff + (uint32_t)(mh * 32 * 528);
    const uint4* W4 = (const uint4*)g_Wbf;             // W_MAT_U4 uint4 per matrix
    const int wfoff = nq * 2048 + lane;                // uint4 units

    float acc[2][8][4];

    // ---- Q ----
    mma_gemm(sb + SM_P, W4 + wfoff, acc, aoffG);
    #pragma unroll
    for (int mf = 0; mf < 2; mf++)
        #pragma unroll
        for (int nf = 0; nf < 8; nf++)
            #pragma unroll
            for (int rr = 0; rr < 2; rr++) {
                int r = mh * 32 + mf * 16 + r0 + rr * 8;
                int c = nq * 64 + nf * 8 + c0;
                *(uint32_t*)(sm + SM_Q + r * 528 + c * 2) =
                    bfx2(acc[mf][nf][rr*2] + sBias[c], acc[mf][nf][rr*2+1] + sBias[c+1]);
            }

    // ---- K ----
    mma_gemm(sb + SM_P, W4 + W_MAT_U4 + wfoff, acc, aoffG);
    #pragma unroll
    for (int mf = 0; mf < 2; mf++)
        #pragma unroll
        for (int nf = 0; nf < 8; nf++)
            #pragma unroll
            for (int rr = 0; rr < 2; rr++) {
                int r = mh * 32 + mf * 16 + r0 + rr * 8;
                int c = nq * 64 + nf * 8 + c0;
                *(uint32_t*)(sm + SM_K + r * 528 + c * 2) =
                    bfx2(acc[mf][nf][rr*2] + sBias[256+c], acc[mf][nf][rr*2+1] + sBias[256+c+1]);
            }

    // ---- V (V' = (xWv+b)*0.1 + x*0.95 -> R, and V^T bf16) ----
    mma_gemm(sb + SM_P, W4 + 2 * W_MAT_U4 + wfoff, acc, aoffG);
    #pragma unroll
    for (int mf = 0; mf < 2; mf++)
        #pragma unroll
        for (int nf = 0; nf < 8; nf++)
            #pragma unroll
            for (int rr = 0; rr < 2; rr++) {
                int r = mh * 32 + mf * 16 + r0 + rr * 8;
                if (r < NTOK) {
                    int c = nq * 64 + nf * 8 + c0;
                    float v0 = (acc[mf][nf][rr*2]   + sBias[512+c])   * 0.1f + R[r*RST+c]   * 0.95f;
                    float v1 = (acc[mf][nf][rr*2+1] + sBias[512+c+1]) * 0.1f + R[r*RST+c+1] * 0.95f;
                    R[r*RST+c] = v0; R[r*RST+c+1] = v1;
                    *(__nv_bfloat16*)(sm + SM_VT + c * 144 + r * 2)       = __float2bfloat16(v0);
                    *(__nv_bfloat16*)(sm + SM_VT + (c + 1) * 144 + r * 2) = __float2bfloat16(v1);
                }
            }
    __syncthreads();

    // ---- scores + in-register softmax -> P (bf16, per-head tiles in SM_P) ----
    const int mfs = w & 3, hw = w >> 2;
    #pragma unroll
    for (int p = 0; p < 2; p++) {
        int h = 2 * p + hw;
        float sc[7][4];
        #pragma unroll
        for (int nf = 0; nf < 7; nf++)
            #pragma unroll
            for (int q = 0; q < 4; q++) sc[nf][q] = 0.0f;

        uint32_t qbase = sb + SM_Q + (uint32_t)(mfs * 16 * 528) + aoff + (uint32_t)(h * 128);
        uint32_t kb    = sb + SM_K + (uint32_t)((lane & 7) * 528) + (uint32_t)(h * 128)
                       + (uint32_t)(((lane >> 3) & 1) * 16);
        #pragma unroll
        for (int ks = 0; ks < 4; ks++) {
            uint32_t a[4];
            ldsm4(a, qbase + ks * 32);
            #pragma unroll
            for (int nf = 0; nf < 7; nf++) {
                uint32_t b[2];
                ldsm2(b, kb + (uint32_t)(nf * 8 * 528) + ks * 32);
                mma16816(sc[nf], a, b);
            }
        }
        #pragma unroll
        for (int half = 0; half < 2; half++) {
            int r = mfs * 16 + r0 + half * 8;
            float vv[14];
            float m = -1e30f;
            #pragma unroll
            for (int nf = 0; nf < 7; nf++)
                #pragma unroll
                for (int j = 0; j < 2; j++) {
                    int kk = nf * 8 + c0 + j;
                    float s = (kk < NTOK) ? sc[nf][half*2 + j] * 0.125f : -1e30f;
                    vv[nf*2 + j] = s;
                    m = fmaxf(m, s);
                }
            m = fmaxf(m, __shfl_xor_sync(0xFFFFFFFFu, m, 1));
            m = fmaxf(m, __shfl_xor_sync(0xFFFFFFFFu, m, 2));
            float sum = 0.0f;
            #pragma unroll
            for (int t = 0; t < 14; t++) {
                float e = (vv[t] > -1e29f) ? __expf(vv[t] - m) : 0.0f;
                vv[t] = e; sum += e;
            }
            sum += __shfl_xor_sync(0xFFFFFFFFu, sum, 1);
            sum += __shfl_xor_sync(0xFFFFFFFFu, sum, 2);
            float inv = 1.0f / sum;
            #pragma unroll
            for (int nf = 0; nf < 7; nf++) {
                uint32_t pk = (r < NTOK) ? bfx2(vv[nf*2] * inv, vv[nf*2+1] * inv) : 0u;
                *(uint32_t*)(sm + SM_P + h * 9216 + r * 144 + (nf * 8 + c0) * 2) = pk;
            }
        }
    }
    __syncthreads();

    // ---- PV: out = P @ V'  ; x2 = out*0.1 + R*0.95 -> R, bf16 tile in SM_Q ----
    {
        const int nfr = (w >> 2) * 4;
        const uint32_t poff = (uint32_t)((iq + (gq & 1) * 8) * 144 + ((gq >> 1) * 8) * 2);
        #pragma unroll
        for (int h = 0; h < 4; h++) {
            float pa[4][4];
            #pragma unroll
            for (int nf = 0; nf < 4; nf++)
                #pragma unroll
                for (int q = 0; q < 4; q++) pa[nf][q] = 0.0f;

            uint32_t pbase = sb + SM_P + (uint32_t)(h * 9216 + mfs * 16 * 144) + poff;
            uint32_t vb = sb + SM_VT + (uint32_t)((h * 64 + nfr * 8 + (lane & 7)) * 144)
                        + (uint32_t)(((lane >> 3) & 1) * 16);
            #pragma unroll
            for (int ks = 0; ks < 4; ks++) {
                uint32_t a[4];
                ldsm4(a, pbase + ks * 32);
                #pragma unroll
                for (int nf = 0; nf < 4; nf++) {
                    uint32_t b[2];
                    ldsm2(b, vb + (uint32_t)(nf * 8 * 144) + ks * 32);
                    mma16816(pa[nf], a, b);
                }
            }
            #pragma unroll
            for (int nf = 0; nf < 4; nf++)
                #pragma unroll
                for (int rr = 0; rr < 2; rr++) {
                    int r = mfs * 16 + r0 + rr * 8;
                    int c = h * 64 + nfr * 8 + nf * 8 + c0;
                    if (r < NTOK) {
                        float a0 = pa[nf][rr*2]   * 0.1f + R[r*RST+c]   * 0.95f;
                        float a1 = pa[nf][rr*2+1] * 0.1f + R[r*RST+c+1] * 0.95f;
                        R[r*RST+c] = a0; R[r*RST+c+1] = a1;
                        *(uint32_t*)(sm + SM_Q + r * 528 + c * 2) = bfx2(a0, a1);
                    } else {
                        *(uint32_t*)(sm + SM_Q + r * 528 + c * 2) = 0u;
                    }
                }
        }
    }
    __syncthreads();

    // ---- FFN in: t2 = (x2 Wfi + b)*0.1 + x2*0.95 ; t3 = (sig(t2)-0.5)*0.1 + t2*0.95 ----
    mma_gemm(sb + SM_Q, W4 + 3 * W_MAT_U4 + wfoff, acc, aoffG);
    __syncthreads();           // all reads of x2 tile done before overwrite
    #pragma unroll
    for (int mf = 0; mf < 2; mf++)
        #pragma unroll
        for (int nf = 0; nf < 8; nf++)
            #pragma unroll
            for (int rr = 0; rr < 2; rr++) {
                int r = mh * 32 + mf * 16 + r0 + rr * 8;
                int c = nq * 64 + nf * 8 + c0;
                if (r < NTOK) {
                    float t2a = (acc[mf][nf][rr*2]   + sBias[768+c])   * 0.1f + R[r*RST+c]   * 0.95f;
                    float t2b = (acc[mf][nf][rr*2+1] + sBias[768+c+1]) * 0.1f + R[r*RST+c+1] * 0.95f;
                    float t3a = (1.0f/(1.0f + __expf(-t2a)) - 0.5f) * 0.1f + t2a * 0.95f;
                    float t3b = (1.0f/(1.0f + __expf(-t2b)) - 0.5f) * 0.1f + t2b * 0.95f;
                    R[r*RST+c] = t3a; R[r*RST+c+1] = t3b;
                    *(uint32_t*)(sm + SM_Q + r * 528 + c * 2) = bfx2(t3a, t3b);
                } else {
                    *(uint32_t*)(sm + SM_Q + r * 528 + c * 2) = 0u;
                }
            }
    __syncthreads();

    // ---- FFN out: out = (t3 Wfo + b)*0.1 + t3*0.95 ----
    mma_gemm(sb + SM_Q, W4 + 4 * W_MAT_U4 + wfoff, acc, aoffG);
    #pragma unroll
    for (int mf = 0; mf < 2; mf++)
        #pragma unroll
        for (int nf = 0; nf < 8; nf++)
            #pragma unroll
            for (int rr = 0; rr < 2; rr++) {
                int r = mh * 32 + mf * 16 + r0 + rr * 8;
                if (r < NTOK) {
                    int c = nq * 64 + nf * 8 + c0;
                    ob[r*DIM + c]   = (acc[mf][nf][rr*2]   + sBias[1024+c])   * 0.1f + R[r*RST+c]   * 0.95f;
                    ob[r*DIM + c+1] = (acc[mf][nf][rr*2+1] + sBias[1024+c+1]) * 0.1f + R[r*RST+c+1] * 0.95f;
                }
            }
}

// ---------------------------------------------------------------------------
extern "C" void kernel_launch(void* const* d_in, const int* in_sizes, int n_in,
                              void* d_out, int out_size)
{
    std_kernel<<<5 * DIM + 5, 256>>>(
        (const float*)d_in[1], (const float*)d_in[2],
        (const float*)d_in[3], (const float*)d_in[4],
        (const float*)d_in[5], (const float*)d_in[6],
        (const float*)d_in[7], (const float*)d_in[8],
        (const float*)d_in[9], (const float*)d_in[10]);

    cudaFuncSetAttribute(irmb_kernel,
                         cudaFuncAttributeMaxDynamicSharedMemorySize, SMEM_TOTAL);
    irmb_kernel<<<NB, 256, SMEM_TOTAL>>>((const float*)d_in[0], (float*)d_out);
}

// round 9
// speedup vs baseline: 1.1983x; 1.1983x over previous
#include <cuda_runtime.h>
#include <cuda_bf16.h>
#include <math.h>
#include <stdint.h>

#define DIM  256
#define NH   4
#define HC   64
#define NTOK 49
#define NB   4096

// Standardized weights in ks-paired mma-FRAGMENT order:
// uint4 index = (nblk*8 + kp)*32 + lane ; uint4 = {ks_even half0, ks_even half1,
//                                                  ks_odd half0,  ks_odd half1}
// For col c, k: nblk=c>>3, lane=(c&7)*4+((k>>1)&3), kp=k>>5, kodd=(k>>4)&1,
//               half=(k>>3)&1, par=k&1.
__device__ __align__(16) __nv_bfloat16 g_Wbf[5][DIM * DIM];
__device__ float g_b[5][DIM];

#define W_MAT_U4 8192   // uint4 per 256x256 bf16 matrix

// ---------------------------------------------------------------------------
// Prologue: weight standardization -> ks-paired fragment-ordered bf16
// ---------------------------------------------------------------------------
__global__ __launch_bounds__(256) void std_kernel(
    const float* __restrict__ qw, const float* __restrict__ qb,
    const float* __restrict__ kw, const float* __restrict__ kb,
    const float* __restrict__ vw, const float* __restrict__ vb,
    const float* __restrict__ fiw, const float* __restrict__ fib,
    const float* __restrict__ fow, const float* __restrict__ fob)
{
    const float* wptr[5] = {qw, kw, vw, fiw, fow};
    const float* bptr[5] = {qb, kb, vb, fib, fob};
    __shared__ float s_sum[8], s_sq[8];
    int bx = blockIdx.x, t = threadIdx.x;

    float val;
    if (bx < 5 * DIM) val = wptr[bx >> 8][(bx & 255) * DIM + t];
    else              val = bptr[bx - 5 * DIM][t];

    float s = val, q = val * val;
    #pragma unroll
    for (int o = 16; o > 0; o >>= 1) {
        s += __shfl_xor_sync(0xFFFFFFFFu, s, o);
        q += __shfl_xor_sync(0xFFFFFFFFu, q, o);
    }
    if ((t & 31) == 0) { s_sum[t >> 5] = s; s_sq[t >> 5] = q; }
    __syncthreads();
    int h = t >> 6;
    float sum = s_sum[2*h] + s_sum[2*h+1];
    float sq  = s_sq [2*h] + s_sq [2*h+1];
    float mean = sum * (1.0f/64.0f);
    float var  = fmaxf(sq * (1.0f/64.0f) - mean*mean, 0.0f);
    float r    = (val - mean) / (sqrtf(var) * 16.0f);

    if (bx < 5 * DIM) {
        int m = bx >> 8, k = bx & 255, c = t;
        int kp   = k >> 5;
        int kodd = (k >> 4) & 1;
        int half = (k >> 3) & 1;
        int pos2 = (k >> 1) & 3;
        int par  = k & 1;
        int lane = (c & 7) * 4 + pos2;
        int nblk = c >> 3;
        size_t idx = ((size_t)(((nblk * 8 + kp) * 32 + lane)) << 3)
                   + (size_t)(kodd * 4 + half * 2 + par);
        ((__nv_bfloat16*)g_Wbf)[(size_t)m * DIM * DIM + idx] = __float2bfloat16(r);
    } else {
        g_b[bx - 5 * DIM][t] = r;
    }
}

// ---------------------------------------------------------------------------
// PTX helpers (baseline PTX only: ldmatrix + mma.sync, sm_80+)
// ---------------------------------------------------------------------------
__device__ __forceinline__ uint32_t s2u(const void* p) {
    uint32_t a;
    asm("{ .reg .u64 t; cvta.to.shared.u64 t, %1; cvt.u32.u64 %0, t; }" : "=r"(a) : "l"(p));
    return a;
}
__device__ __forceinline__ void ldsm4(uint32_t* r, uint32_t a) {
    asm volatile("ldmatrix.sync.aligned.m8n8.x4.shared.b16 {%0,%1,%2,%3}, [%4];"
                 : "=r"(r[0]), "=r"(r[1]), "=r"(r[2]), "=r"(r[3]) : "r"(a));
}
__device__ __forceinline__ void ldsm2(uint32_t* r, uint32_t a) {
    asm volatile("ldmatrix.sync.aligned.m8n8.x2.shared.b16 {%0,%1}, [%2];"
                 : "=r"(r[0]), "=r"(r[1]) : "r"(a));
}
__device__ __forceinline__ void mma16816(float* d, const uint32_t* a, const uint32_t* b) {
    asm volatile("mma.sync.aligned.m16n8k16.row.col.f32.bf16.bf16.f32 "
                 "{%0,%1,%2,%3}, {%4,%5,%6,%7}, {%8,%9}, {%0,%1,%2,%3};"
                 : "+f"(d[0]), "+f"(d[1]), "+f"(d[2]), "+f"(d[3])
                 : "r"(a[0]), "r"(a[1]), "r"(a[2]), "r"(a[3]), "r"(b[0]), "r"(b[1]));
}
__device__ __forceinline__ uint32_t bfx2(float lo, float hi) {   // low half = lo
    uint32_t r;
    asm("cvt.rn.bf16x2.f32 %0, %1, %2;" : "=r"(r) : "f"(hi), "f"(lo));
    return r;
}

// ---------------------------------------------------------------------------
// smem layout (bytes). Activation tiles: 64 rows x 264 bf16, stride 528 B.
// P tiles: per head 64 x 72 bf16 (stride 144 B). VT: 256 x 72 bf16.
// ---------------------------------------------------------------------------
#define RST 260
#define SM_R    0        // 49*260*4 = 50960
#define SM_P    51072    // 36864 : x tile (64x264), later P tiles 4 x (64x72)
#define SM_Q    87936    // 33792 : Q tile, later x2 / t3 tile
#define SM_K    121728   // 33792 : K tile
#define SM_VT   155520   // 36864 : V^T 256 x 72
#define SM_BIAS 192384   // 5120  : biases fp32 [5][256]
#define SMEM_TOTAL 197504

#define NT 512   // threads per CTA (16 warps)

// One 64x256x256 GEMM with 16 warps: warp (mh = w>>3) x (nq = w&7)
// computes m32 x n32. A from smem (stride 528, rows mh*32..); B via LDG.128
// from ks-paired fragment-ordered W (nblk = nq*4+nf). 1-deep B double-buffer.
__device__ __forceinline__ void mma_gemm(uint32_t aBase, const uint4* __restrict__ Wf,
                                         float acc[2][4][4], uint32_t aoffG)
{
    #pragma unroll
    for (int mf = 0; mf < 2; mf++)
        #pragma unroll
        for (int nf = 0; nf < 4; nf++)
            #pragma unroll
            for (int q = 0; q < 4; q++) acc[mf][nf][q] = 0.0f;

    uint4 breg[2][4];
    #pragma unroll
    for (int nf = 0; nf < 4; nf++) breg[0][nf] = __ldg(Wf + nf * 256);

    #pragma unroll
    for (int kp = 0; kp < 8; kp++) {
        const int cur = kp & 1, nxt = cur ^ 1;
        if (kp < 7) {
            #pragma unroll
            for (int nf = 0; nf < 4; nf++)
                breg[nxt][nf] = __ldg(Wf + nf * 256 + (kp + 1) * 32);
        }
        uint32_t a0[2][4], a1[2][4];
        #pragma unroll
        for (int mf = 0; mf < 2; mf++) {
            ldsm4(a0[mf], aBase + aoffG + (uint32_t)(mf * 16 * 528 + (2*kp)   * 32));
            ldsm4(a1[mf], aBase + aoffG + (uint32_t)(mf * 16 * 528 + (2*kp+1) * 32));
        }
        #pragma unroll
        for (int nf = 0; nf < 4; nf++) {
            uint32_t b0[2] = { breg[cur][nf].x, breg[cur][nf].y };
            uint32_t b1[2] = { breg[cur][nf].z, breg[cur][nf].w };
            #pragma unroll
            for (int mf = 0; mf < 2; mf++) {
                mma16816(acc[mf][nf], a0[mf], b0);
                mma16816(acc[mf][nf], a1[mf], b1);
            }
        }
    }
}

__global__ __launch_bounds__(NT, 1) void irmb_kernel(
    const float* __restrict__ x, float* __restrict__ out)
{
    extern __shared__ char sm[];
    const uint32_t sb = s2u(sm);
    const int tid = threadIdx.x, w = tid >> 5, lane = tid & 31;

    float* R = (float*)(sm + SM_R);
    float* sBias = (float*)(sm + SM_BIAS);

    // zero x/P buffer + VT, load biases
    {
        uint32_t* z = (uint32_t*)(sm + SM_P);
        for (int i = tid; i < 9216; i += NT) z[i] = 0;
        uint32_t* z2 = (uint32_t*)(sm + SM_VT);
        for (int i = tid; i < 9216; i += NT) z2[i] = 0;
        const float* gb = (const float*)g_b;
        for (int i = tid; i < 1280; i += NT) sBias[i] = gb[i];
    }
    const float* xb = x + (size_t)blockIdx.x * (NTOK * DIM);
    float* ob = out + (size_t)blockIdx.x * (NTOK * DIM);
    __syncthreads();

    for (int i = tid; i < NTOK * DIM; i += NT) {
        int r = i >> 8, c = i & 255;
        float v = xb[i];
        R[r * RST + c] = v;
        *(__nv_bfloat16*)(sm + SM_P + r * 528 + c * 2) = __float2bfloat16(v);
    }
    __syncthreads();

    // lane-mapping constants
    const int gq = lane >> 3, iq = lane & 7;
    const uint32_t aoff = (uint32_t)((iq + (gq & 1) * 8) * 528 + ((gq >> 1) * 8) * 2);
    const int r0 = lane >> 2, c0 = 2 * (lane & 3);
    // GEMM warp tiling: mh = m-half (rows mh*32..), nq = n-eighth (cols nq*32..)
    const int mh = w >> 3, nq = w & 7;
    const uint32_t aoffG = aoff + (uint32_t)(mh * 32 * 528);
    const uint4* W4 = (const uint4*)g_Wbf;             // W_MAT_U4 uint4 per matrix
    const int wfoff = nq * 1024 + lane;                // uint4 units (nblk=nq*4)

    float acc[2][4][4];

    // ---- Q ----
    mma_gemm(sb + SM_P, W4 + wfoff, acc, aoffG);
    #pragma unroll
    for (int mf = 0; mf < 2; mf++)
        #pragma unroll
        for (int nf = 0; nf < 4; nf++)
            #pragma unroll
            for (int rr = 0; rr < 2; rr++) {
                int r = mh * 32 + mf * 16 + r0 + rr * 8;
                int c = nq * 32 + nf * 8 + c0;
                *(uint32_t*)(sm + SM_Q + r * 528 + c * 2) =
                    bfx2(acc[mf][nf][rr*2] + sBias[c], acc[mf][nf][rr*2+1] + sBias[c+1]);
            }

    // ---- K ----
    mma_gemm(sb + SM_P, W4 + W_MAT_U4 + wfoff, acc, aoffG);
    #pragma unroll
    for (int mf = 0; mf < 2; mf++)
        #pragma unroll
        for (int nf = 0; nf < 4; nf++)
            #pragma unroll
            for (int rr = 0; rr < 2; rr++) {
                int r = mh * 32 + mf * 16 + r0 + rr * 8;
                int c = nq * 32 + nf * 8 + c0;
                *(uint32_t*)(sm + SM_K + r * 528 + c * 2) =
                    bfx2(acc[mf][nf][rr*2] + sBias[256+c], acc[mf][nf][rr*2+1] + sBias[256+c+1]);
            }

    // ---- V (V' = (xWv+b)*0.1 + x*0.95 -> R, and V^T bf16) ----
    mma_gemm(sb + SM_P, W4 + 2 * W_MAT_U4 + wfoff, acc, aoffG);
    #pragma unroll
    for (int mf = 0; mf < 2; mf++)
        #pragma unroll
        for (int nf = 0; nf < 4; nf++)
            #pragma unroll
            for (int rr = 0; rr < 2; rr++) {
                int r = mh * 32 + mf * 16 + r0 + rr * 8;
                if (r < NTOK) {
                    int c = nq * 32 + nf * 8 + c0;
                    float v0 = (acc[mf][nf][rr*2]   + sBias[512+c])   * 0.1f + R[r*RST+c]   * 0.95f;
                    float v1 = (acc[mf][nf][rr*2+1] + sBias[512+c+1]) * 0.1f + R[r*RST+c+1] * 0.95f;
                    R[r*RST+c] = v0; R[r*RST+c+1] = v1;
                    *(__nv_bfloat16*)(sm + SM_VT + c * 144 + r * 2)       = __float2bfloat16(v0);
                    *(__nv_bfloat16*)(sm + SM_VT + (c + 1) * 144 + r * 2) = __float2bfloat16(v1);
                }
            }
    __syncthreads();

    // ---- scores + in-register softmax -> P. 16 warps: (mfs = w&3, h = w>>2) ----
    const int mfs = w & 3, hh = w >> 2;
    {
        float sc[7][4];
        #pragma unroll
        for (int nf = 0; nf < 7; nf++)
            #pragma unroll
            for (int q = 0; q < 4; q++) sc[nf][q] = 0.0f;

        uint32_t qbase = sb + SM_Q + (uint32_t)(mfs * 16 * 528) + aoff + (uint32_t)(hh * 128);
        uint32_t kb    = sb + SM_K + (uint32_t)((lane & 7) * 528) + (uint32_t)(hh * 128)
                       + (uint32_t)(((lane >> 3) & 1) * 16);
        #pragma unroll
        for (int ks = 0; ks < 4; ks++) {
            uint32_t a[4];
            ldsm4(a, qbase + ks * 32);
            #pragma unroll
            for (int nf = 0; nf < 7; nf++) {
                uint32_t b[2];
                ldsm2(b, kb + (uint32_t)(nf * 8 * 528) + ks * 32);
                mma16816(sc[nf], a, b);
            }
        }
        #pragma unroll
        for (int half = 0; half < 2; half++) {
            int r = mfs * 16 + r0 + half * 8;
            float vv[14];
            float m = -1e30f;
            #pragma unroll
            for (int nf = 0; nf < 7; nf++)
                #pragma unroll
                for (int j = 0; j < 2; j++) {
                    int kk = nf * 8 + c0 + j;
                    float s = (kk < NTOK) ? sc[nf][half*2 + j] * 0.125f : -1e30f;
                    vv[nf*2 + j] = s;
                    m = fmaxf(m, s);
                }
            m = fmaxf(m, __shfl_xor_sync(0xFFFFFFFFu, m, 1));
            m = fmaxf(m, __shfl_xor_sync(0xFFFFFFFFu, m, 2));
            float sum = 0.0f;
            #pragma unroll
            for (int t = 0; t < 14; t++) {
                float e = (vv[t] > -1e29f) ? __expf(vv[t] - m) : 0.0f;
                vv[t] = e; sum += e;
            }
            sum += __shfl_xor_sync(0xFFFFFFFFu, sum, 1);
            sum += __shfl_xor_sync(0xFFFFFFFFu, sum, 2);
            float inv = 1.0f / sum;
            #pragma unroll
            for (int nf = 0; nf < 7; nf++) {
                uint32_t pk = (r < NTOK) ? bfx2(vv[nf*2] * inv, vv[nf*2+1] * inv) : 0u;
                *(uint32_t*)(sm + SM_P + hh * 9216 + r * 144 + (nf * 8 + c0) * 2) = pk;
            }
        }
    }
    __syncthreads();

    // ---- PV: warp (mfs, hh): rows mfs*16.., all 64 cols of head hh ----
    {
        const uint32_t poff = (uint32_t)((iq + (gq & 1) * 8) * 144 + ((gq >> 1) * 8) * 2);
        float pa[8][4];
        #pragma unroll
        for (int nf = 0; nf < 8; nf++)
            #pragma unroll
            for (int q = 0; q < 4; q++) pa[nf][q] = 0.0f;

        uint32_t pbase = sb + SM_P + (uint32_t)(hh * 9216 + mfs * 16 * 144) + poff;
        #pragma unroll
        for (int ks = 0; ks < 4; ks++) {
            uint32_t a[4];
            ldsm4(a, pbase + ks * 32);
            #pragma unroll
            for (int nf = 0; nf < 8; nf++) {
                uint32_t b[2];
                uint32_t vb = sb + SM_VT
                    + (uint32_t)((hh * 64 + nf * 8 + (lane & 7)) * 144)
                    + (uint32_t)(((lane >> 3) & 1) * 16);
                ldsm2(b, vb + ks * 32);
                mma16816(pa[nf], a, b);
            }
        }
        #pragma unroll
        for (int nf = 0; nf < 8; nf++)
            #pragma unroll
            for (int rr = 0; rr < 2; rr++) {
                int r = mfs * 16 + r0 + rr * 8;
                int c = hh * 64 + nf * 8 + c0;
                if (r < NTOK) {
                    float a0 = pa[nf][rr*2]   * 0.1f + R[r*RST+c]   * 0.95f;
                    float a1 = pa[nf][rr*2+1] * 0.1f + R[r*RST+c+1] * 0.95f;
                    R[r*RST+c] = a0; R[r*RST+c+1] = a1;
                    *(uint32_t*)(sm + SM_Q + r * 528 + c * 2) = bfx2(a0, a1);
                } else {
                    *(uint32_t*)(sm + SM_Q + r * 528 + c * 2) = 0u;
                }
            }
    }
    __syncthreads();

    // ---- FFN in: t2 = (x2 Wfi + b)*0.1 + x2*0.95 ; t3 = (sig(t2)-0.5)*0.1 + t2*0.95 ----
    mma_gemm(sb + SM_Q, W4 + 3 * W_MAT_U4 + wfoff, acc, aoffG);
    __syncthreads();           // all reads of x2 tile done before overwrite
    #pragma unroll
    for (int mf = 0; mf < 2; mf++)
        #pragma unroll
        for (int nf = 0; nf < 4; nf++)
            #pragma unroll
            for (int rr = 0; rr < 2; rr++) {
                int r = mh * 32 + mf * 16 + r0 + rr * 8;
                int c = nq * 32 + nf * 8 + c0;
                if (r < NTOK) {
                    float t2a = (acc[mf][nf][rr*2]   + sBias[768+c])   * 0.1f + R[r*RST+c]   * 0.95f;
                    float t2b = (acc[mf][nf][rr*2+1] + sBias[768+c+1]) * 0.1f + R[r*RST+c+1] * 0.95f;
                    float t3a = (1.0f/(1.0f + __expf(-t2a)) - 0.5f) * 0.1f + t2a * 0.95f;
                    float t3b = (1.0f/(1.0f + __expf(-t2b)) - 0.5f) * 0.1f + t2b * 0.95f;
                    R[r*RST+c] = t3a; R[r*RST+c+1] = t3b;
                    *(uint32_t*)(sm + SM_Q + r * 528 + c * 2) = bfx2(t3a, t3b);
                } else {
                    *(uint32_t*)(sm + SM_Q + r * 528 + c * 2) = 0u;
                }
            }
    __syncthreads();

    // ---- FFN out: out = (t3 Wfo + b)*0.1 + t3*0.95 ----
    mma_gemm(sb + SM_Q, W4 + 4 * W_MAT_U4 + wfoff, acc, aoffG);
    #pragma unroll
    for (int mf = 0; mf < 2; mf++)
        #pragma unroll
        for (int nf = 0; nf < 4; nf++)
            #pragma unroll
            for (int rr = 0; rr < 2; rr++) {
                int r = mh * 32 + mf * 16 + r0 + rr * 8;
                if (r < NTOK) {
                    int c = nq * 32 + nf * 8 + c0;
                    ob[r*DIM + c]   = (acc[mf][nf][rr*2]   + sBias[1024+c])   * 0.1f + R[r*RST+c]   * 0.95f;
                    ob[r*DIM + c+1] = (acc[mf][nf][rr*2+1] + sBias[1024+c+1]) * 0.1f + R[r*RST+c+1] * 0.95f;
                }
            }
}

// ---------------------------------------------------------------------------
extern "C" void kernel_launch(void* const* d_in, const int* in_sizes, int n_in,
                              void* d_out, int out_size)
{
    std_kernel<<<5 * DIM + 5, 256>>>(
        (const float*)d_in[1], (const float*)d_in[2],
        (const float*)d_in[3], (const float*)d_in[4],
        (const float*)d_in[5], (const float*)d_in[6],
        (const float*)d_in[7], (const float*)d_in[8],
        (const float*)d_in[9], (const float*)d_in[10]);

    cudaFuncSetAttribute(irmb_kernel,
                         cudaFuncAttributeMaxDynamicSharedMemorySize, SMEM_TOTAL);
    irmb_kernel<<<NB, NT, SMEM_TOTAL>>>((const float*)d_in[0], (float*)d_out);
}